// round 14
// baseline (speedup 1.0000x reference)
#include <cuda_runtime.h>
#include <cuda_fp16.h>
#include <cstdint>

// Problem constants
#define FEAT   224
#define NPAT   32
#define H_IMG  256
#define W_IMG  512
#define W_PAT  1024
#define S_CAM  (H_IMG * W_IMG)   // 131072
#define S_PROJ W_PAT             // 1024
#define F2     (FEAT * FEAT)
#define NCAM   (H_IMG * W_IMG * NPAT)   // 4194304

// Scratch (device globals) — all GEMM operands fp16
__device__ __half g_X    [S_CAM * FEAT];   // cam running x / final Y
__device__ __half g_Hc   [S_CAM * FEAT];   // cam hidden
__device__ float  g_stats[S_CAM * 2];      // per-row {sum, sumsq}
__device__ __half g_camh [NCAM];           // fp16-rounded cam_code
__device__ __half g_Pp   [S_PROJ * FEAT];  // proj p
__device__ __half g_Xp   [S_PROJ * FEAT];  // proj running x / Yp
__device__ __half g_Hp   [S_PROJ * FEAT];  // proj hidden / Bnorm
__device__ __half g_W0c  [2 * F2];
__device__ __half g_W1c  [2 * F2];
__device__ __half g_W0p  [2 * F2];
__device__ __half g_W1p  [2 * F2];

// ---------------------------------------------------------------------------
// Helpers
// ---------------------------------------------------------------------------
__device__ __forceinline__ uint32_t smem_u32(const void* p) {
    uint32_t a;
    asm("{ .reg .u64 t; cvta.to.shared.u64 t, %1; cvt.u32.u64 %0, t; }"
        : "=r"(a) : "l"(p));
    return a;
}
__device__ __forceinline__ void cp16(uint32_t dst, const void* src) {
    asm volatile("cp.async.cg.shared.global [%0], [%1], 16;"
                 :: "r"(dst), "l"(src) : "memory");
}
__device__ __forceinline__ void cp_commit() {
    asm volatile("cp.async.commit_group;" ::: "memory");
}
__device__ __forceinline__ void cp_wait1() {
    asm volatile("cp.async.wait_group 1;" ::: "memory");
}
__device__ __forceinline__ void cp_wait0() {
    asm volatile("cp.async.wait_group 0;" ::: "memory");
}

// ---------------------------------------------------------------------------
// Merged preprocessing: round cam + 4 weight tensors + build proj P
// ---------------------------------------------------------------------------
#define PRE_W0 (NCAM)
#define PRE_W1 (PRE_W0 + 2 * F2)
#define PRE_W2 (PRE_W1 + 2 * F2)
#define PRE_W3 (PRE_W2 + 2 * F2)
#define PRE_PP (PRE_W3 + 2 * F2)
#define PRE_TOT (PRE_PP + S_PROJ * FEAT)

__global__ void preproc(const float* __restrict__ cam,
                        const float* __restrict__ proj,
                        const float* __restrict__ w0c, const float* __restrict__ w1c,
                        const float* __restrict__ w0p, const float* __restrict__ w1p,
                        __half* __restrict__ CH, __half* __restrict__ Pp,
                        __half* __restrict__ W0c, __half* __restrict__ W1c,
                        __half* __restrict__ W0p, __half* __restrict__ W1p) {
    int idx = blockIdx.x * blockDim.x + threadIdx.x;
    if (idx < PRE_W0) {
        CH[idx] = __float2half_rn(cam[idx]);
    } else if (idx < PRE_W1) {
        int i = idx - PRE_W0; W0c[i] = __float2half_rn(w0c[i]);
    } else if (idx < PRE_W2) {
        int i = idx - PRE_W1; W1c[i] = __float2half_rn(w1c[i]);
    } else if (idx < PRE_W3) {
        int i = idx - PRE_W2; W0p[i] = __float2half_rn(w0p[i]);
    } else if (idx < PRE_PP) {
        int i = idx - PRE_W3; W1p[i] = __float2half_rn(w1p[i]);
    } else if (idx < PRE_TOT) {
        int i = idx - PRE_PP;
        int m = i / FEAT;
        int f = i - m * FEAT;
        int j = f / NPAT;
        int k = f - j * NPAT;
        int mp = m + j - 3;
        mp = mp < 0 ? 0 : (mp > W_PAT - 1 ? W_PAT - 1 : mp);
        Pp[i] = __float2half_rn(proj[k * W_PAT + mp]);
    }
}

// ---------------------------------------------------------------------------
// MLP GEMM: exact-fit 128x224 block tile, 448 threads (14 warps 2m x 7n,
// warp tile 64x32). FP16 m16n8k16 mma, fp32 accum, cp.async 3-stage.
// Stage: A region 128x64B (8KB) + B region 224x64B (14KB) = 22528 B.
// Swizzle (64B rows, 4 granules): slot = g ^ ((r>>1)&3) — in-row bijection,
// and for fixed g over 8 consecutive rows the slot-index mod 8 is
// {x, x+4 : x in 0..3} = 8 distinct -> conflict-free ldmatrix.
// MODE bits: 1 +bias, 2 relu, 4 +Res, 16 +Res2, 128 emit per-row stats.
// (always stores fp16)
// ---------------------------------------------------------------------------
#define BK        32
#define MST_BYTES 22528
#define MB_OFF    8192
#define NSTAGE    3
#define MSTAT_B   (NSTAGE * MST_BYTES)        // 67584
#define MLP_SMEM  (MSTAT_B + 1024)            // 68608
#define GS        232                          // residual stage row stride (halves)

struct GArg {
    const __half *A, *W, *Res, *Res2, *camA;
    const float *bias;
    __half *C;
    float *stats;
    int M;
    int agather, resgather, res2gather;
};

template <int MODE>
__global__ void __launch_bounds__(448, 1)
tgemm_mlp(GArg a0, GArg a1) {
    extern __shared__ char smc[];
    __half* smh = (__half*)smc;
    float* smstat = (float*)(smc + MSTAT_B);
    const uint32_t sb = smem_u32(smc);

    const int t    = threadIdx.x;
    const int lane = t & 31;
    const int wid  = t >> 5;     // 0..13
    const int wm   = wid & 1;
    const int wn   = wid >> 1;   // 0..6
    const int nch  = FEAT / BK;  // 7

    const int tiles0 = a0.M >> 7;
    GArg g;
    int m0;
    if ((int)blockIdx.y < tiles0) { g = a0; m0 = blockIdx.y * 128; }
    else                          { g = a1; m0 = (blockIdx.y - tiles0) * 128; }

    if (MODE & 128) {
        if (t < 256) smstat[t] = 0.f;
    }

    // --- loader mapping: 1408 granules/chunk over 448 threads (i<4) ---
    const __half* srcB[4];
    uint32_t dstO[4];
    int isA[4], wb[4], valid[4];
#pragma unroll
    for (int i = 0; i < 4; i++) {
        int idx = t + 448 * i;
        valid[i] = idx < 1408;
        if (!valid[i]) { srcB[i] = nullptr; dstO[i] = 0; isA[i] = 0; wb[i] = 0; continue; }
        if (idx < 512) {
            int r = idx >> 2, gq = idx & 3;
            isA[i] = 1;
            if (g.agather) {
                wb[i]   = (m0 & (W_IMG - 1)) + r;
                srcB[i] = g.camA + ((size_t)(m0 & ~(W_IMG - 1)) << 5) + gq * 8;
            } else {
                wb[i]   = 0;
                srcB[i] = g.A + (size_t)(m0 + r) * FEAT + gq * 8;
            }
            dstO[i] = (uint32_t)r * 64 + (((uint32_t)gq ^ ((r >> 1) & 3)) << 4);
        } else {
            int e = idx - 512;
            int r = e >> 2, gq = e & 3;
            isA[i] = 0; wb[i] = 0;
            srcB[i] = g.W + (size_t)r * FEAT + gq * 8;
            dstO[i] = MB_OFF + (uint32_t)r * 64 + (((uint32_t)gq ^ ((r >> 1) & 3)) << 4);
        }
    }

    auto loadAB = [&](int ch) {
        uint32_t so = (uint32_t)(ch % NSTAGE) * MST_BYTES;
#pragma unroll
        for (int i = 0; i < 4; i++) {
            if (!valid[i]) continue;
            const __half* src;
            if (isA[i] && g.agather) {
                int wc = wb[i] + ch - 3;
                wc = wc < 0 ? 0 : (wc > W_IMG - 1 ? W_IMG - 1 : wc);
                src = srcB[i] + (size_t)wc * NPAT;
            } else {
                src = srcB[i] + (size_t)ch * BK;
            }
            cp16(sb + so + dstO[i], src);
        }
    };

    // --- ldmatrix lane mappings ---
    const int a_roff = (((lane >> 3) & 1) << 3) + (lane & 7);
    const int a_kb   = lane >> 4;
    const int b_roff = (((lane >> 4) & 1) << 3) + (lane & 7);
    const int b_kb   = (lane >> 3) & 1;

    float c[4][4][4];
#pragma unroll
    for (int i = 0; i < 4; i++)
#pragma unroll
        for (int j = 0; j < 4; j++)
#pragma unroll
            for (int r = 0; r < 4; r++) c[i][j][r] = 0.0f;

    auto do_chunk = [&](int ch) {
        const uint32_t st = sb + (uint32_t)(ch % NSTAGE) * MST_BYTES;
#pragma unroll
        for (int ks = 0; ks < 2; ks++) {
            uint32_t af[4][4];
#pragma unroll
            for (int mf = 0; mf < 4; mf++) {
                int row = wm * 64 + mf * 16 + a_roff;
                int gk  = 2 * ks + a_kb;
                uint32_t addr = st + (uint32_t)row * 64 +
                                (((uint32_t)gk ^ ((row >> 1) & 3)) << 4);
                asm volatile(
                    "ldmatrix.sync.aligned.m8n8.x4.shared.b16 {%0,%1,%2,%3}, [%4];"
                    : "=r"(af[mf][0]), "=r"(af[mf][1]),
                      "=r"(af[mf][2]), "=r"(af[mf][3])
                    : "r"(addr));
            }
            uint32_t bf[4][2];
#pragma unroll
            for (int p = 0; p < 2; p++) {
                int row = wn * 32 + p * 16 + b_roff;
                int gk  = 2 * ks + b_kb;
                uint32_t addr = st + MB_OFF + (uint32_t)row * 64 +
                                (((uint32_t)gk ^ ((row >> 1) & 3)) << 4);
                asm volatile(
                    "ldmatrix.sync.aligned.m8n8.x4.shared.b16 {%0,%1,%2,%3}, [%4];"
                    : "=r"(bf[2 * p][0]), "=r"(bf[2 * p][1]),
                      "=r"(bf[2 * p + 1][0]), "=r"(bf[2 * p + 1][1])
                    : "r"(addr));
            }
#pragma unroll
            for (int mf = 0; mf < 4; mf++)
#pragma unroll
                for (int nf = 0; nf < 4; nf++) {
                    asm volatile(
                        "mma.sync.aligned.m16n8k16.row.col.f32.f16.f16.f32 "
                        "{%0,%1,%2,%3}, {%4,%5,%6,%7}, {%8,%9}, {%0,%1,%2,%3};"
                        : "+f"(c[mf][nf][0]), "+f"(c[mf][nf][1]),
                          "+f"(c[mf][nf][2]), "+f"(c[mf][nf][3])
                        : "r"(af[mf][0]), "r"(af[mf][1]),
                          "r"(af[mf][2]), "r"(af[mf][3]),
                          "r"(bf[nf][0]), "r"(bf[nf][1]));
                }
        }
    };

    loadAB(0); cp_commit();
    loadAB(1); cp_commit();
    for (int ch = 0; ch < nch; ch++) {
        if (ch + 1 < nch) cp_wait1(); else cp_wait0();
        __syncthreads();
        if (ch + 2 < nch) loadAB(ch + 2);
        cp_commit();
        do_chunk(ch);
    }

    // --- stage residual P-tile (fp16, 128 x 224) into free pipeline smem ---
    const int dogather = ((MODE & 4) && g.resgather) ||
                         ((MODE & 16) && g.res2gather);
    if (dogather) {
        __syncthreads();
#pragma unroll
        for (int i = 0; i < 10; i++) {
            int idx = t + 448 * i;     // padded 128 rows x 32 q-slots
            if (idx < 4096) {
                int r = idx >> 5;
                int q = idx & 31;
                if (q < 28) {
                    int s  = m0 + r;
                    int j  = q >> 2;
                    int wc = (s & (W_IMG - 1)) + j - 3;
                    wc = wc < 0 ? 0 : (wc > W_IMG - 1 ? W_IMG - 1 : wc);
                    const __half* src = g.camA +
                        (((size_t)(s & ~(W_IMG - 1)) + wc) << 5) + (q & 3) * 8;
                    cp16(sb + (uint32_t)r * (GS * 2) + q * 16, src);
                }
            }
        }
        cp_commit();
        cp_wait0();
        __syncthreads();
    }

    const int lq = lane >> 2;
    const int lr = lane & 3;

    float ss[8], qq[8];
    if (MODE & 128) {
#pragma unroll
        for (int e = 0; e < 8; e++) { ss[e] = 0.f; qq[e] = 0.f; }
    }

    // --- epilogue (all cols valid: 7 n-slabs x 32 = 224) ---
#pragma unroll
    for (int mf = 0; mf < 4; mf++) {
        int row = m0 + wm * 64 + mf * 16 + lq;
#pragma unroll
        for (int nf = 0; nf < 4; nf++) {
            int col = wn * 32 + nf * 8 + lr * 2;
            float b0 = 0.f, b1 = 0.f;
            if (MODE & 1) { b0 = g.bias[col]; b1 = g.bias[col + 1]; }
#pragma unroll
            for (int half_ = 0; half_ < 2; half_++) {
                int r = row + half_ * 8;
                float v0 = c[mf][nf][half_ * 2 + 0];
                float v1 = c[mf][nf][half_ * 2 + 1];
                if (MODE & 1) { v0 += b0; v1 += b1; }
                if (MODE & 2) { v0 = fmaxf(v0, 0.f); v1 = fmaxf(v1, 0.f); }
                size_t o = (size_t)r * FEAT + col;
                if (MODE & 4) {
                    float2 rv;
                    if (g.resgather)
                        rv = __half22float2(*(const __half2*)(smh + (r - m0) * GS + col));
                    else
                        rv = __half22float2(*(const __half2*)(g.Res + o));
                    v0 += rv.x; v1 += rv.y;
                }
                if (MODE & 16) {
                    float2 rv;
                    if (g.res2gather)
                        rv = __half22float2(*(const __half2*)(smh + (r - m0) * GS + col));
                    else
                        rv = __half22float2(*(const __half2*)(g.Res2 + o));
                    v0 += rv.x; v1 += rv.y;
                }
                __half2 hv = __floats2half2_rn(v0, v1);
                *((__half2*)(g.C + o)) = hv;
                if (MODE & 128) {
                    float2 fr = __half22float2(hv);
                    int e = mf * 2 + half_;
                    ss[e] += fr.x + fr.y;
                    qq[e] += fr.x * fr.x + fr.y * fr.y;
                }
            }
        }
    }

    if (MODE & 128) {
#pragma unroll
        for (int e = 0; e < 8; e++) {
            ss[e] += __shfl_xor_sync(0xffffffffu, ss[e], 1);
            ss[e] += __shfl_xor_sync(0xffffffffu, ss[e], 2);
            qq[e] += __shfl_xor_sync(0xffffffffu, qq[e], 1);
            qq[e] += __shfl_xor_sync(0xffffffffu, qq[e], 2);
        }
        __syncthreads();
        if (lr == 0) {
#pragma unroll
            for (int e = 0; e < 8; e++) {
                int rl = wm * 64 + (e >> 1) * 16 + lq + (e & 1) * 8;
                atomicAdd(&smstat[rl * 2 + 0], ss[e]);
                atomicAdd(&smstat[rl * 2 + 1], qq[e]);
            }
        }
        __syncthreads();
        if (t < 128 && g.stats) {
            *(float2*)(g.stats + (size_t)(m0 + t) * 2) =
                make_float2(smstat[t * 2], smstat[t * 2 + 1]);
        }
    }
}

// ---------------------------------------------------------------------------
// Final ZNCC GEMM: 128-thread CTAs, 4 warps 2m x 2n, warp tile 64x64,
// 3 CTAs/SM. out[s,m] = inv_a[s] * (Y[s,:] . Bnorm[m,:]), fp32 out.
// Stage = 128 rows x 128 B (A|B per row, 8 granules, g ^ (r&7) swizzle).
// ---------------------------------------------------------------------------
#define FST_BYTES 16384
#define FIN_SMEM  (NSTAGE * FST_BYTES + 1024)   // 50176

__global__ void __launch_bounds__(128, 3)
tgemm_fin(const __half* __restrict__ A, const __half* __restrict__ W,
          const float* __restrict__ statsin, float* __restrict__ C) {
    extern __shared__ char smc[];
    const uint32_t sb = smem_u32(smc);

    const int t    = threadIdx.x;
    const int lane = t & 31;
    const int wid  = t >> 5;
    const int wm   = wid & 1;
    const int wn   = wid >> 1;
    const int n0   = blockIdx.x * 128;
    const int m0   = blockIdx.y * 128;
    const int nch  = FEAT / BK;
    const int N    = W_PAT;

    const int r0 = t >> 2;
    const int gq = t & 3;
    const __half* Abase = A + (size_t)(m0 + r0) * FEAT + gq * 8;
    const __half* Bbase = W + (size_t)(n0 + r0) * FEAT + gq * 8;
    const uint32_t Adst0 = sb + (uint32_t)r0 * 128 + (((uint32_t)gq       ^ (r0 & 7)) << 4);
    const uint32_t Bdst0 = sb + (uint32_t)r0 * 128 + (((uint32_t)(gq + 4) ^ (r0 & 7)) << 4);

    auto loadAB = [&](int ch) {
        uint32_t so = (uint32_t)(ch % NSTAGE) * FST_BYTES;
#pragma unroll
        for (int i = 0; i < 4; i++) {
            cp16(Adst0 + so + i * 4096,
                 Abase + (size_t)(32 * i) * FEAT + (size_t)ch * BK);
            cp16(Bdst0 + so + i * 4096,
                 Bbase + (size_t)(32 * i) * FEAT + (size_t)ch * BK);
        }
    };

    const int a_roff = (((lane >> 3) & 1) << 3) + (lane & 7);
    const int a_kb   = lane >> 4;
    const int b_roff = (((lane >> 4) & 1) << 3) + (lane & 7);
    const int b_kb   = (lane >> 3) & 1;

    float c[4][8][4];
#pragma unroll
    for (int i = 0; i < 4; i++)
#pragma unroll
        for (int j = 0; j < 8; j++)
#pragma unroll
            for (int r = 0; r < 4; r++) c[i][j][r] = 0.0f;

    auto do_chunk = [&](int ch) {
        const uint32_t st_b = sb + (uint32_t)(ch % NSTAGE) * FST_BYTES;
#pragma unroll
        for (int ks = 0; ks < 2; ks++) {
            uint32_t af[4][4];
#pragma unroll
            for (int mf = 0; mf < 4; mf++) {
                int row = wm * 64 + mf * 16 + a_roff;
                int gk  = 2 * ks + a_kb;
                uint32_t addr = st_b + (uint32_t)row * 128 +
                                (((uint32_t)gk ^ (row & 7)) << 4);
                asm volatile(
                    "ldmatrix.sync.aligned.m8n8.x4.shared.b16 {%0,%1,%2,%3}, [%4];"
                    : "=r"(af[mf][0]), "=r"(af[mf][1]),
                      "=r"(af[mf][2]), "=r"(af[mf][3])
                    : "r"(addr));
            }
#pragma unroll
            for (int p = 0; p < 4; p++) {
                uint32_t bf0, bf1, bf2, bf3;
                int row = wn * 64 + p * 16 + b_roff;
                int gk  = 4 + 2 * ks + b_kb;
                uint32_t addr = st_b + (uint32_t)row * 128 +
                                (((uint32_t)gk ^ (row & 7)) << 4);
                asm volatile(
                    "ldmatrix.sync.aligned.m8n8.x4.shared.b16 {%0,%1,%2,%3}, [%4];"
                    : "=r"(bf0), "=r"(bf1), "=r"(bf2), "=r"(bf3)
                    : "r"(addr));
#pragma unroll
                for (int mf = 0; mf < 4; mf++) {
                    asm volatile(
                        "mma.sync.aligned.m16n8k16.row.col.f32.f16.f16.f32 "
                        "{%0,%1,%2,%3}, {%4,%5,%6,%7}, {%8,%9}, {%0,%1,%2,%3};"
                        : "+f"(c[mf][2 * p][0]), "+f"(c[mf][2 * p][1]),
                          "+f"(c[mf][2 * p][2]), "+f"(c[mf][2 * p][3])
                        : "r"(af[mf][0]), "r"(af[mf][1]),
                          "r"(af[mf][2]), "r"(af[mf][3]),
                          "r"(bf0), "r"(bf1));
                    asm volatile(
                        "mma.sync.aligned.m16n8k16.row.col.f32.f16.f16.f32 "
                        "{%0,%1,%2,%3}, {%4,%5,%6,%7}, {%8,%9}, {%0,%1,%2,%3};"
                        : "+f"(c[mf][2 * p + 1][0]), "+f"(c[mf][2 * p + 1][1]),
                          "+f"(c[mf][2 * p + 1][2]), "+f"(c[mf][2 * p + 1][3])
                        : "r"(af[mf][0]), "r"(af[mf][1]),
                          "r"(af[mf][2]), "r"(af[mf][3]),
                          "r"(bf2), "r"(bf3));
                }
            }
        }
    };

    loadAB(0); cp_commit();
    loadAB(1); cp_commit();
    for (int ch = 0; ch < nch; ch++) {
        if (ch + 1 < nch) cp_wait1(); else cp_wait0();
        __syncthreads();
        if (ch + 2 < nch) loadAB(ch + 2);
        cp_commit();
        do_chunk(ch);
    }

    const int lq = lane >> 2;
    const int lr = lane & 3;

#pragma unroll
    for (int mf = 0; mf < 4; mf++) {
        int row = m0 + wm * 64 + mf * 16 + lq;
        float2 s0 = *(const float2*)(statsin + (size_t)row * 2);
        float2 s1 = *(const float2*)(statsin + (size_t)(row + 8) * 2);
        float inv0 = rsqrtf(s0.y - s0.x * s0.x * (1.0f / FEAT));
        float inv1 = rsqrtf(s1.y - s1.x * s1.x * (1.0f / FEAT));
#pragma unroll
        for (int nf = 0; nf < 8; nf++) {
            int col = n0 + wn * 64 + nf * 8 + lr * 2;
#pragma unroll
            for (int half_ = 0; half_ < 2; half_++) {
                int r = row + half_ * 8;
                float sc = half_ ? inv1 : inv0;
                float v0 = c[mf][nf][half_ * 2 + 0] * sc;
                float v1 = c[mf][nf][half_ * 2 + 1] * sc;
                *(float2*)(C + (size_t)r * N + col) = make_float2(v0, v1);
            }
        }
    }
}

// ---------------------------------------------------------------------------
// Proj normalize: Bnorm[m,:] = (Y[m,:] - mean) / ||Y - mean||  (fp16 out)
// ---------------------------------------------------------------------------
__global__ void normalize_proj(const __half* __restrict__ Y,
                               __half* __restrict__ Out, int M) {
    int warp = (blockIdx.x * blockDim.x + threadIdx.x) >> 5;
    int lane = threadIdx.x & 31;
    if (warp >= M) return;
    size_t base = (size_t)warp * FEAT;
    float y[7];
    float sum = 0.f;
#pragma unroll
    for (int i = 0; i < 7; i++) {
        y[i] = __half2float(Y[base + lane + i * 32]);
        sum += y[i];
    }
#pragma unroll
    for (int o = 16; o > 0; o >>= 1) sum += __shfl_xor_sync(0xffffffffu, sum, o);
    float mean = sum * (1.0f / FEAT);
    float sq = 0.f;
#pragma unroll
    for (int i = 0; i < 7; i++) {
        y[i] -= mean;
        sq += y[i] * y[i];
    }
#pragma unroll
    for (int o = 16; o > 0; o >>= 1) sq += __shfl_xor_sync(0xffffffffu, sq, o);
    float inv = rsqrtf(sq);
#pragma unroll
    for (int i = 0; i < 7; i++)
        Out[base + lane + i * 32] = __float2half_rn(y[i] * inv);
}

// ---------------------------------------------------------------------------
extern "C" void kernel_launch(void* const* d_in, const int* in_sizes, int n_in,
                              void* d_out, int out_size) {
    const float* cam_code  = (const float*)d_in[0];
    const float* proj_code = (const float*)d_in[1];
    const float* cam_w0 = (const float*)d_in[2];
    const float* cam_b0 = (const float*)d_in[3];
    const float* cam_w1 = (const float*)d_in[4];
    const float* cam_b1 = (const float*)d_in[5];
    const float* proj_w0 = (const float*)d_in[6];
    const float* proj_b0 = (const float*)d_in[7];
    const float* proj_w1 = (const float*)d_in[8];
    const float* proj_b1 = (const float*)d_in[9];
    float* out = (float*)d_out;

    __half *X, *Hc, *CH, *Pp, *Xp, *Hp, *W0c, *W1c, *W0p, *W1p;
    float *ST;
    cudaGetSymbolAddress((void**)&X,   g_X);
    cudaGetSymbolAddress((void**)&Hc,  g_Hc);
    cudaGetSymbolAddress((void**)&ST,  g_stats);
    cudaGetSymbolAddress((void**)&CH,  g_camh);
    cudaGetSymbolAddress((void**)&Pp,  g_Pp);
    cudaGetSymbolAddress((void**)&Xp,  g_Xp);
    cudaGetSymbolAddress((void**)&Hp,  g_Hp);
    cudaGetSymbolAddress((void**)&W0c, g_W0c);
    cudaGetSymbolAddress((void**)&W1c, g_W1c);
    cudaGetSymbolAddress((void**)&W0p, g_W0p);
    cudaGetSymbolAddress((void**)&W1p, g_W1p);

    cudaFuncSetAttribute(tgemm_mlp<3>,   cudaFuncAttributeMaxDynamicSharedMemorySize, MLP_SMEM);
    cudaFuncSetAttribute(tgemm_mlp<5>,   cudaFuncAttributeMaxDynamicSharedMemorySize, MLP_SMEM);
    cudaFuncSetAttribute(tgemm_mlp<149>, cudaFuncAttributeMaxDynamicSharedMemorySize, MLP_SMEM);
    cudaFuncSetAttribute(tgemm_fin,      cudaFuncAttributeMaxDynamicSharedMemorySize, FIN_SMEM);

    // 1) Merged preprocessing
    preproc<<<(PRE_TOT + 255) / 256, 256>>>(cam_code, proj_code,
                                            cam_w0, cam_w1, proj_w0, proj_w1,
                                            CH, Pp, W0c, W1c, W0p, W1p);

    const int TC = S_CAM / 128;   // 1024
    const int TP = S_PROJ / 128;  // 8
    dim3 gmlp(1, TC + TP);        // exact-fit: single N-tile of 224

    GArg c0, p0;
    // layer 0, GEMM 0: H = relu(P @ W0^T + b0); cam P gathered from g_camh
    c0 = {nullptr, W0c, nullptr, nullptr, CH, cam_b0, Hc, nullptr,
          S_CAM,  1, 0, 0};
    p0 = {Pp,      W0p, nullptr, nullptr, nullptr, proj_b0, Hp, nullptr,
          S_PROJ, 0, 0, 0};
    tgemm_mlp<3><<<gmlp, 448, MLP_SMEM>>>(c0, p0);        // bias|relu

    // layer 0, GEMM 1: X = P + H @ W1^T + b1  (cam residual staged gather)
    c0 = {Hc, W1c, nullptr, nullptr, CH, cam_b1, X, nullptr,
          S_CAM,  0, 1, 0};
    p0 = {Hp, W1p, Pp,      nullptr, nullptr, proj_b1, Xp, nullptr,
          S_PROJ, 0, 0, 0};
    tgemm_mlp<5><<<gmlp, 448, MLP_SMEM>>>(c0, p0);        // bias|res

    // layer 1, GEMM 0: H = relu(X @ W0^T + b0)
    c0 = {X,  W0c + F2, nullptr, nullptr, nullptr, cam_b0 + FEAT,  Hc, nullptr,
          S_CAM,  0, 0, 0};
    p0 = {Xp, W0p + F2, nullptr, nullptr, nullptr, proj_b0 + FEAT, Hp, nullptr,
          S_PROJ, 0, 0, 0};
    tgemm_mlp<3><<<gmlp, 448, MLP_SMEM>>>(c0, p0);

    // layer 1, GEMM 1: Y = X + H @ W1^T + b1 + P  (+ per-row stats, cam)
    c0 = {Hc, W1c + F2, X,  nullptr, CH, cam_b1 + FEAT,  X,  ST,
          S_CAM,  0, 0, 1};
    p0 = {Hp, W1p + F2, Xp, Pp,      nullptr, proj_b1 + FEAT, Xp, nullptr,
          S_PROJ, 0, 0, 0};
    tgemm_mlp<149><<<gmlp, 448, MLP_SMEM>>>(c0, p0);      // bias|res|res2|stats

    // 3) Proj normalize (cam stats already emitted)
    normalize_proj<<<(S_PROJ + 7) / 8, 256>>>(Xp, Hp, S_PROJ);

    // 4) ZNCC correlation
    dim3 gfin(W_PAT / 128, TC);
    tgemm_fin<<<gfin, 128, FIN_SMEM>>>(X, Hp, ST, out);
}

// round 15
// speedup vs baseline: 1.1731x; 1.1731x over previous
#include <cuda_runtime.h>
#include <cuda_fp16.h>
#include <cstdint>

// Problem constants
#define FEAT   224
#define NPAT   32
#define H_IMG  256
#define W_IMG  512
#define W_PAT  1024
#define S_CAM  (H_IMG * W_IMG)   // 131072
#define S_PROJ W_PAT             // 1024
#define F2     (FEAT * FEAT)
#define NCAM   (H_IMG * W_IMG * NPAT)   // 4194304

// Scratch (device globals) — all GEMM operands fp16
__device__ __half g_X    [S_CAM * FEAT];   // cam running x / final Y
__device__ __half g_Hc   [S_CAM * FEAT];   // cam hidden
__device__ float  g_stats[S_CAM * 4];      // per-row {s,q} x 2 x-tiles
__device__ __half g_camh [NCAM];           // fp16-rounded cam_code
__device__ __half g_Pp   [S_PROJ * FEAT];  // proj p
__device__ __half g_Xp   [S_PROJ * FEAT];  // proj running x / Yp
__device__ __half g_Hp   [S_PROJ * FEAT];  // proj hidden / Bnorm
__device__ __half g_W0c  [2 * F2];
__device__ __half g_W1c  [2 * F2];
__device__ __half g_W0p  [2 * F2];
__device__ __half g_W1p  [2 * F2];

// ---------------------------------------------------------------------------
// Helpers
// ---------------------------------------------------------------------------
__device__ __forceinline__ uint32_t smem_u32(const void* p) {
    uint32_t a;
    asm("{ .reg .u64 t; cvta.to.shared.u64 t, %1; cvt.u32.u64 %0, t; }"
        : "=r"(a) : "l"(p));
    return a;
}
__device__ __forceinline__ void cp16(uint32_t dst, const void* src) {
    asm volatile("cp.async.cg.shared.global [%0], [%1], 16;"
                 :: "r"(dst), "l"(src) : "memory");
}
__device__ __forceinline__ void cp_commit() {
    asm volatile("cp.async.commit_group;" ::: "memory");
}
__device__ __forceinline__ void cp_wait1() {
    asm volatile("cp.async.wait_group 1;" ::: "memory");
}
__device__ __forceinline__ void cp_wait0() {
    asm volatile("cp.async.wait_group 0;" ::: "memory");
}

// ---------------------------------------------------------------------------
// Merged preprocessing: round cam + 4 weight tensors + build proj P
// ---------------------------------------------------------------------------
#define PRE_W0 (NCAM)
#define PRE_W1 (PRE_W0 + 2 * F2)
#define PRE_W2 (PRE_W1 + 2 * F2)
#define PRE_W3 (PRE_W2 + 2 * F2)
#define PRE_PP (PRE_W3 + 2 * F2)
#define PRE_TOT (PRE_PP + S_PROJ * FEAT)

__global__ void preproc(const float* __restrict__ cam,
                        const float* __restrict__ proj,
                        const float* __restrict__ w0c, const float* __restrict__ w1c,
                        const float* __restrict__ w0p, const float* __restrict__ w1p,
                        __half* __restrict__ CH, __half* __restrict__ Pp,
                        __half* __restrict__ W0c, __half* __restrict__ W1c,
                        __half* __restrict__ W0p, __half* __restrict__ W1p) {
    int idx = blockIdx.x * blockDim.x + threadIdx.x;
    if (idx < PRE_W0) {
        CH[idx] = __float2half_rn(cam[idx]);
    } else if (idx < PRE_W1) {
        int i = idx - PRE_W0; W0c[i] = __float2half_rn(w0c[i]);
    } else if (idx < PRE_W2) {
        int i = idx - PRE_W1; W1c[i] = __float2half_rn(w1c[i]);
    } else if (idx < PRE_W3) {
        int i = idx - PRE_W2; W0p[i] = __float2half_rn(w0p[i]);
    } else if (idx < PRE_PP) {
        int i = idx - PRE_W3; W1p[i] = __float2half_rn(w1p[i]);
    } else if (idx < PRE_TOT) {
        int i = idx - PRE_PP;
        int m = i / FEAT;
        int f = i - m * FEAT;
        int j = f / NPAT;
        int k = f - j * NPAT;
        int mp = m + j - 3;
        mp = mp < 0 ? 0 : (mp > W_PAT - 1 ? W_PAT - 1 : mp);
        Pp[i] = __float2half_rn(proj[k * W_PAT + mp]);
    }
}

// ---------------------------------------------------------------------------
// MLP GEMM: exact-fit 128x112 block tile (2 x-tiles cover N=224 exactly).
// 128 threads, 4 warps 2m x 2n, warp tile 64x56, 3 CTAs/SM.
// FP16 m16n8k16 mma, fp32 accum, cp.async 3-stage + ldmatrix.
// Stage: A region 128x64B (8192) + B region 112x64B (7168) = 15360 B.
// 64B-row swizzle: slot = g ^ ((r>>1)&3) (in-row bijection; 8 consecutive
// rows at fixed g hit 8 distinct 16B chunks -> conflict-free ldmatrix).
// MODE bits: 1 +bias, 2 relu, 4 +Res, 16 +Res2, 128 emit per-row stats.
// Always stores fp16.
// ---------------------------------------------------------------------------
#define BK        32
#define MA_BYTES  8192
#define MST_BYTES 15360
#define NSTAGE    3
#define MSTAT_B   (NSTAGE * MST_BYTES)        // 46080
#define MLP_SMEM  (MSTAT_B + 1024)            // 47104
#define GS        120                          // residual stage row stride (halves)

struct GArg {
    const __half *A, *W, *Res, *Res2, *camA;
    const float *bias;
    __half *C;
    float *stats;
    int M;
    int agather, resgather, res2gather;
};

template <int MODE>
__global__ void __launch_bounds__(128, 3)
tgemm_mlp(GArg a0, GArg a1) {
    extern __shared__ char smc[];
    __half* smh = (__half*)smc;
    float* smstat = (float*)(smc + MSTAT_B);
    const uint32_t sb = smem_u32(smc);

    const int t    = threadIdx.x;
    const int lane = t & 31;
    const int wid  = t >> 5;     // 0..3
    const int wm   = wid & 1;    // 64-row slab
    const int wn   = wid >> 1;   // 56-col slab
    const int n0   = blockIdx.x * 112;
    const int nch  = FEAT / BK;  // 7

    const int tiles0 = a0.M >> 7;
    GArg g;
    int m0;
    if ((int)blockIdx.y < tiles0) { g = a0; m0 = blockIdx.y * 128; }
    else                          { g = a1; m0 = (blockIdx.y - tiles0) * 128; }

    if (MODE & 128) {
        smstat[t] = 0.f;
        smstat[t + 128] = 0.f;
    }

    // --- loader mapping ---
    // A: 512 granules = 128 threads x 4 (rows r0+32i); B: 448 = rows r0+32i,
    // i=3 only for t<64. Swizzle slot invariant across +32 rows.
    const int r0 = t >> 2;      // 0..31
    const int gq = t & 3;
    const __half* Abase;
    int wb0 = 0;
    if (g.agather) {
        wb0   = (m0 & (W_IMG - 1)) + r0;
        Abase = g.camA + ((size_t)(m0 & ~(W_IMG - 1)) << 5) + gq * 8;
    } else {
        Abase = g.A + (size_t)(m0 + r0) * FEAT + gq * 8;
    }
    const __half* Bbase = g.W + (size_t)(n0 + r0) * FEAT + gq * 8;
    const uint32_t slot  = (((uint32_t)gq ^ ((r0 >> 1) & 3)) << 4);
    const uint32_t Adst0 = sb + (uint32_t)r0 * 64 + slot;
    const uint32_t Bdst0 = sb + MA_BYTES + (uint32_t)r0 * 64 + slot;

    auto loadAB = [&](int ch) {
        uint32_t so = (uint32_t)(ch % NSTAGE) * MST_BYTES;
#pragma unroll
        for (int i = 0; i < 4; i++) {
            const __half* asrc;
            if (g.agather) {
                int wc = wb0 + 32 * i + ch - 3;
                wc = wc < 0 ? 0 : (wc > W_IMG - 1 ? W_IMG - 1 : wc);
                asrc = Abase + (size_t)wc * NPAT;
            } else {
                asrc = Abase + (size_t)(32 * i) * FEAT + (size_t)ch * BK;
            }
            cp16(Adst0 + so + i * 2048, asrc);
        }
#pragma unroll
        for (int i = 0; i < 4; i++) {
            if (i < 3 || t < 64)
                cp16(Bdst0 + so + i * 2048,
                     Bbase + (size_t)(32 * i) * FEAT + (size_t)ch * BK);
        }
    };

    // --- ldmatrix lane mappings ---
    const int a_roff = (((lane >> 3) & 1) << 3) + (lane & 7);
    const int a_kb   = lane >> 4;
    const int b_roff = (((lane >> 4) & 1) << 3) + (lane & 7);
    const int b_kb   = (lane >> 3) & 1;
    const int b2_roff = lane & 7;             // x2 variant
    const int b2_kb   = (lane >> 3) & 1;

    float c[4][7][4];
#pragma unroll
    for (int i = 0; i < 4; i++)
#pragma unroll
        for (int j = 0; j < 7; j++)
#pragma unroll
            for (int r = 0; r < 4; r++) c[i][j][r] = 0.0f;

    auto do_chunk = [&](int ch) {
        const uint32_t st = sb + (uint32_t)(ch % NSTAGE) * MST_BYTES;
#pragma unroll
        for (int ks = 0; ks < 2; ks++) {
            uint32_t af[4][4];
#pragma unroll
            for (int mf = 0; mf < 4; mf++) {
                int row = wm * 64 + mf * 16 + a_roff;
                int gk  = 2 * ks + a_kb;
                uint32_t addr = st + (uint32_t)row * 64 +
                                (((uint32_t)gk ^ ((row >> 1) & 3)) << 4);
                asm volatile(
                    "ldmatrix.sync.aligned.m8n8.x4.shared.b16 {%0,%1,%2,%3}, [%4];"
                    : "=r"(af[mf][0]), "=r"(af[mf][1]),
                      "=r"(af[mf][2]), "=r"(af[mf][3])
                    : "r"(addr));
            }
            uint32_t bf[7][2];
#pragma unroll
            for (int p = 0; p < 3; p++) {     // nf = 2p, 2p+1
                int row = wn * 56 + p * 16 + b_roff;
                int gk  = 2 * ks + b_kb;
                uint32_t addr = st + MA_BYTES + (uint32_t)row * 64 +
                                (((uint32_t)gk ^ ((row >> 1) & 3)) << 4);
                asm volatile(
                    "ldmatrix.sync.aligned.m8n8.x4.shared.b16 {%0,%1,%2,%3}, [%4];"
                    : "=r"(bf[2 * p][0]), "=r"(bf[2 * p][1]),
                      "=r"(bf[2 * p + 1][0]), "=r"(bf[2 * p + 1][1])
                    : "r"(addr));
            }
            {   // nf = 6 via x2
                int row = wn * 56 + 48 + b2_roff;
                int gk  = 2 * ks + b2_kb;
                uint32_t addr = st + MA_BYTES + (uint32_t)row * 64 +
                                (((uint32_t)gk ^ ((row >> 1) & 3)) << 4);
                asm volatile(
                    "ldmatrix.sync.aligned.m8n8.x2.shared.b16 {%0,%1}, [%2];"
                    : "=r"(bf[6][0]), "=r"(bf[6][1])
                    : "r"(addr));
            }
#pragma unroll
            for (int mf = 0; mf < 4; mf++)
#pragma unroll
                for (int nf = 0; nf < 7; nf++) {
                    asm volatile(
                        "mma.sync.aligned.m16n8k16.row.col.f32.f16.f16.f32 "
                        "{%0,%1,%2,%3}, {%4,%5,%6,%7}, {%8,%9}, {%0,%1,%2,%3};"
                        : "+f"(c[mf][nf][0]), "+f"(c[mf][nf][1]),
                          "+f"(c[mf][nf][2]), "+f"(c[mf][nf][3])
                        : "r"(af[mf][0]), "r"(af[mf][1]),
                          "r"(af[mf][2]), "r"(af[mf][3]),
                          "r"(bf[nf][0]), "r"(bf[nf][1]));
                }
        }
    };

    loadAB(0); cp_commit();
    loadAB(1); cp_commit();
    for (int ch = 0; ch < nch; ch++) {
        if (ch + 1 < nch) cp_wait1(); else cp_wait0();
        __syncthreads();
        if (ch + 2 < nch) loadAB(ch + 2);
        cp_commit();
        do_chunk(ch);
    }

    // --- stage residual P-tile (fp16, 128 x 112) into free pipeline smem ---
    const int dogather = ((MODE & 4) && g.resgather) ||
                         ((MODE & 16) && g.res2gather);
    if (dogather) {
        __syncthreads();
#pragma unroll
        for (int i = 0; i < 16; i++) {
            int idx = t + 128 * i;     // 128 rows x 16 q-slots (q<14 valid)
            int r = idx >> 4;
            int q = idx & 15;
            if (q < 14) {
                int s  = m0 + r;
                int gcol = n0 + q * 8;
                int j  = gcol >> 5;
                int wc = (s & (W_IMG - 1)) + j - 3;
                wc = wc < 0 ? 0 : (wc > W_IMG - 1 ? W_IMG - 1 : wc);
                const __half* src = g.camA +
                    (((size_t)(s & ~(W_IMG - 1)) + wc) << 5) + (gcol & 31);
                cp16(sb + (uint32_t)r * (GS * 2) + q * 16, src);
            }
        }
        cp_commit();
        cp_wait0();
        __syncthreads();
    }

    const int lq = lane >> 2;
    const int lr = lane & 3;

    float ss[8], qq[8];
    if (MODE & 128) {
#pragma unroll
        for (int e = 0; e < 8; e++) { ss[e] = 0.f; qq[e] = 0.f; }
    }

    // --- epilogue (all 112 cols valid) ---
#pragma unroll
    for (int mf = 0; mf < 4; mf++) {
        int row = m0 + wm * 64 + mf * 16 + lq;
#pragma unroll
        for (int nf = 0; nf < 7; nf++) {
            int col  = wn * 56 + nf * 8 + lr * 2;   // local 0..111
            int gcol = n0 + col;
            float b0 = 0.f, b1 = 0.f;
            if (MODE & 1) { b0 = g.bias[gcol]; b1 = g.bias[gcol + 1]; }
#pragma unroll
            for (int half_ = 0; half_ < 2; half_++) {
                int r = row + half_ * 8;
                float v0 = c[mf][nf][half_ * 2 + 0];
                float v1 = c[mf][nf][half_ * 2 + 1];
                if (MODE & 1) { v0 += b0; v1 += b1; }
                if (MODE & 2) { v0 = fmaxf(v0, 0.f); v1 = fmaxf(v1, 0.f); }
                size_t o = (size_t)r * FEAT + gcol;
                if (MODE & 4) {
                    float2 rv;
                    if (g.resgather)
                        rv = __half22float2(*(const __half2*)(smh + (r - m0) * GS + col));
                    else
                        rv = __half22float2(*(const __half2*)(g.Res + o));
                    v0 += rv.x; v1 += rv.y;
                }
                if (MODE & 16) {
                    float2 rv;
                    if (g.res2gather)
                        rv = __half22float2(*(const __half2*)(smh + (r - m0) * GS + col));
                    else
                        rv = __half22float2(*(const __half2*)(g.Res2 + o));
                    v0 += rv.x; v1 += rv.y;
                }
                __half2 hv = __floats2half2_rn(v0, v1);
                *((__half2*)(g.C + o)) = hv;
                if (MODE & 128) {
                    float2 fr = __half22float2(hv);
                    int e = mf * 2 + half_;
                    ss[e] += fr.x + fr.y;
                    qq[e] += fr.x * fr.x + fr.y * fr.y;
                }
            }
        }
    }

    if (MODE & 128) {
#pragma unroll
        for (int e = 0; e < 8; e++) {
            ss[e] += __shfl_xor_sync(0xffffffffu, ss[e], 1);
            ss[e] += __shfl_xor_sync(0xffffffffu, ss[e], 2);
            qq[e] += __shfl_xor_sync(0xffffffffu, qq[e], 1);
            qq[e] += __shfl_xor_sync(0xffffffffu, qq[e], 2);
        }
        __syncthreads();
        if (lr == 0) {
#pragma unroll
            for (int e = 0; e < 8; e++) {
                int rl = wm * 64 + (e >> 1) * 16 + lq + (e & 1) * 8;
                atomicAdd(&smstat[rl * 2 + 0], ss[e]);
                atomicAdd(&smstat[rl * 2 + 1], qq[e]);
            }
        }
        __syncthreads();
        if (g.stats) {
            *(float2*)(g.stats + (size_t)(m0 + t) * 4 + blockIdx.x * 2) =
                make_float2(smstat[t * 2], smstat[t * 2 + 1]);
        }
    }
}

// ---------------------------------------------------------------------------
// Final ZNCC GEMM: 128-thread CTAs, 4 warps 2m x 2n, warp tile 64x64,
// 3 CTAs/SM. out[s,m] = inv_a[s] * (Y[s,:] . Bnorm[m,:]), fp32 out.
// Stage = 128 rows x 128 B (A|B per row, 8 granules, g ^ (r&7) swizzle).
// ---------------------------------------------------------------------------
#define FST_BYTES 16384
#define FIN_SMEM  (NSTAGE * FST_BYTES + 1024)   // 50176

__global__ void __launch_bounds__(128, 3)
tgemm_fin(const __half* __restrict__ A, const __half* __restrict__ W,
          const float* __restrict__ statsin, float* __restrict__ C) {
    extern __shared__ char smc[];
    const uint32_t sb = smem_u32(smc);

    const int t    = threadIdx.x;
    const int lane = t & 31;
    const int wid  = t >> 5;
    const int wm   = wid & 1;
    const int wn   = wid >> 1;
    const int n0   = blockIdx.x * 128;
    const int m0   = blockIdx.y * 128;
    const int nch  = FEAT / BK;
    const int N    = W_PAT;

    const int r0 = t >> 2;
    const int gq = t & 3;
    const __half* Abase = A + (size_t)(m0 + r0) * FEAT + gq * 8;
    const __half* Bbase = W + (size_t)(n0 + r0) * FEAT + gq * 8;
    const uint32_t Adst0 = sb + (uint32_t)r0 * 128 + (((uint32_t)gq       ^ (r0 & 7)) << 4);
    const uint32_t Bdst0 = sb + (uint32_t)r0 * 128 + (((uint32_t)(gq + 4) ^ (r0 & 7)) << 4);

    auto loadAB = [&](int ch) {
        uint32_t so = (uint32_t)(ch % NSTAGE) * FST_BYTES;
#pragma unroll
        for (int i = 0; i < 4; i++) {
            cp16(Adst0 + so + i * 4096,
                 Abase + (size_t)(32 * i) * FEAT + (size_t)ch * BK);
            cp16(Bdst0 + so + i * 4096,
                 Bbase + (size_t)(32 * i) * FEAT + (size_t)ch * BK);
        }
    };

    const int a_roff = (((lane >> 3) & 1) << 3) + (lane & 7);
    const int a_kb   = lane >> 4;
    const int b_roff = (((lane >> 4) & 1) << 3) + (lane & 7);
    const int b_kb   = (lane >> 3) & 1;

    float c[4][8][4];
#pragma unroll
    for (int i = 0; i < 4; i++)
#pragma unroll
        for (int j = 0; j < 8; j++)
#pragma unroll
            for (int r = 0; r < 4; r++) c[i][j][r] = 0.0f;

    auto do_chunk = [&](int ch) {
        const uint32_t st_b = sb + (uint32_t)(ch % NSTAGE) * FST_BYTES;
#pragma unroll
        for (int ks = 0; ks < 2; ks++) {
            uint32_t af[4][4];
#pragma unroll
            for (int mf = 0; mf < 4; mf++) {
                int row = wm * 64 + mf * 16 + a_roff;
                int gk  = 2 * ks + a_kb;
                uint32_t addr = st_b + (uint32_t)row * 128 +
                                (((uint32_t)gk ^ (row & 7)) << 4);
                asm volatile(
                    "ldmatrix.sync.aligned.m8n8.x4.shared.b16 {%0,%1,%2,%3}, [%4];"
                    : "=r"(af[mf][0]), "=r"(af[mf][1]),
                      "=r"(af[mf][2]), "=r"(af[mf][3])
                    : "r"(addr));
            }
#pragma unroll
            for (int p = 0; p < 4; p++) {
                uint32_t bf0, bf1, bf2, bf3;
                int row = wn * 64 + p * 16 + b_roff;
                int gk  = 4 + 2 * ks + b_kb;
                uint32_t addr = st_b + (uint32_t)row * 128 +
                                (((uint32_t)gk ^ (row & 7)) << 4);
                asm volatile(
                    "ldmatrix.sync.aligned.m8n8.x4.shared.b16 {%0,%1,%2,%3}, [%4];"
                    : "=r"(bf0), "=r"(bf1), "=r"(bf2), "=r"(bf3)
                    : "r"(addr));
#pragma unroll
                for (int mf = 0; mf < 4; mf++) {
                    asm volatile(
                        "mma.sync.aligned.m16n8k16.row.col.f32.f16.f16.f32 "
                        "{%0,%1,%2,%3}, {%4,%5,%6,%7}, {%8,%9}, {%0,%1,%2,%3};"
                        : "+f"(c[mf][2 * p][0]), "+f"(c[mf][2 * p][1]),
                          "+f"(c[mf][2 * p][2]), "+f"(c[mf][2 * p][3])
                        : "r"(af[mf][0]), "r"(af[mf][1]),
                          "r"(af[mf][2]), "r"(af[mf][3]),
                          "r"(bf0), "r"(bf1));
                    asm volatile(
                        "mma.sync.aligned.m16n8k16.row.col.f32.f16.f16.f32 "
                        "{%0,%1,%2,%3}, {%4,%5,%6,%7}, {%8,%9}, {%0,%1,%2,%3};"
                        : "+f"(c[mf][2 * p + 1][0]), "+f"(c[mf][2 * p + 1][1]),
                          "+f"(c[mf][2 * p + 1][2]), "+f"(c[mf][2 * p + 1][3])
                        : "r"(af[mf][0]), "r"(af[mf][1]),
                          "r"(af[mf][2]), "r"(af[mf][3]),
                          "r"(bf2), "r"(bf3));
                }
            }
        }
    };

    loadAB(0); cp_commit();
    loadAB(1); cp_commit();
    for (int ch = 0; ch < nch; ch++) {
        if (ch + 1 < nch) cp_wait1(); else cp_wait0();
        __syncthreads();
        if (ch + 2 < nch) loadAB(ch + 2);
        cp_commit();
        do_chunk(ch);
    }

    const int lq = lane >> 2;
    const int lr = lane & 3;

#pragma unroll
    for (int mf = 0; mf < 4; mf++) {
        int row = m0 + wm * 64 + mf * 16 + lq;
        float4 s0v = *(const float4*)(statsin + (size_t)row * 4);
        float4 s1v = *(const float4*)(statsin + (size_t)(row + 8) * 4);
        float sa = s0v.x + s0v.z, qa = s0v.y + s0v.w;
        float sb2 = s1v.x + s1v.z, qb = s1v.y + s1v.w;
        float inv0 = rsqrtf(qa - sa * sa * (1.0f / FEAT));
        float inv1 = rsqrtf(qb - sb2 * sb2 * (1.0f / FEAT));
#pragma unroll
        for (int nf = 0; nf < 8; nf++) {
            int col = n0 + wn * 64 + nf * 8 + lr * 2;
#pragma unroll
            for (int half_ = 0; half_ < 2; half_++) {
                int r = row + half_ * 8;
                float sc = half_ ? inv1 : inv0;
                float v0 = c[mf][nf][half_ * 2 + 0] * sc;
                float v1 = c[mf][nf][half_ * 2 + 1] * sc;
                *(float2*)(C + (size_t)r * N + col) = make_float2(v0, v1);
            }
        }
    }
}

// ---------------------------------------------------------------------------
// Proj normalize: Bnorm[m,:] = (Y[m,:] - mean) / ||Y - mean||  (fp16 out)
// ---------------------------------------------------------------------------
__global__ void normalize_proj(const __half* __restrict__ Y,
                               __half* __restrict__ Out, int M) {
    int warp = (blockIdx.x * blockDim.x + threadIdx.x) >> 5;
    int lane = threadIdx.x & 31;
    if (warp >= M) return;
    size_t base = (size_t)warp * FEAT;
    float y[7];
    float sum = 0.f;
#pragma unroll
    for (int i = 0; i < 7; i++) {
        y[i] = __half2float(Y[base + lane + i * 32]);
        sum += y[i];
    }
#pragma unroll
    for (int o = 16; o > 0; o >>= 1) sum += __shfl_xor_sync(0xffffffffu, sum, o);
    float mean = sum * (1.0f / FEAT);
    float sq = 0.f;
#pragma unroll
    for (int i = 0; i < 7; i++) {
        y[i] -= mean;
        sq += y[i] * y[i];
    }
#pragma unroll
    for (int o = 16; o > 0; o >>= 1) sq += __shfl_xor_sync(0xffffffffu, sq, o);
    float inv = rsqrtf(sq);
#pragma unroll
    for (int i = 0; i < 7; i++)
        Out[base + lane + i * 32] = __float2half_rn(y[i] * inv);
}

// ---------------------------------------------------------------------------
extern "C" void kernel_launch(void* const* d_in, const int* in_sizes, int n_in,
                              void* d_out, int out_size) {
    const float* cam_code  = (const float*)d_in[0];
    const float* proj_code = (const float*)d_in[1];
    const float* cam_w0 = (const float*)d_in[2];
    const float* cam_b0 = (const float*)d_in[3];
    const float* cam_w1 = (const float*)d_in[4];
    const float* cam_b1 = (const float*)d_in[5];
    const float* proj_w0 = (const float*)d_in[6];
    const float* proj_b0 = (const float*)d_in[7];
    const float* proj_w1 = (const float*)d_in[8];
    const float* proj_b1 = (const float*)d_in[9];
    float* out = (float*)d_out;

    __half *X, *Hc, *CH, *Pp, *Xp, *Hp, *W0c, *W1c, *W0p, *W1p;
    float *ST;
    cudaGetSymbolAddress((void**)&X,   g_X);
    cudaGetSymbolAddress((void**)&Hc,  g_Hc);
    cudaGetSymbolAddress((void**)&ST,  g_stats);
    cudaGetSymbolAddress((void**)&CH,  g_camh);
    cudaGetSymbolAddress((void**)&Pp,  g_Pp);
    cudaGetSymbolAddress((void**)&Xp,  g_Xp);
    cudaGetSymbolAddress((void**)&Hp,  g_Hp);
    cudaGetSymbolAddress((void**)&W0c, g_W0c);
    cudaGetSymbolAddress((void**)&W1c, g_W1c);
    cudaGetSymbolAddress((void**)&W0p, g_W0p);
    cudaGetSymbolAddress((void**)&W1p, g_W1p);

    cudaFuncSetAttribute(tgemm_mlp<3>,   cudaFuncAttributeMaxDynamicSharedMemorySize, MLP_SMEM);
    cudaFuncSetAttribute(tgemm_mlp<5>,   cudaFuncAttributeMaxDynamicSharedMemorySize, MLP_SMEM);
    cudaFuncSetAttribute(tgemm_mlp<149>, cudaFuncAttributeMaxDynamicSharedMemorySize, MLP_SMEM);
    cudaFuncSetAttribute(tgemm_fin,      cudaFuncAttributeMaxDynamicSharedMemorySize, FIN_SMEM);

    // 1) Merged preprocessing
    preproc<<<(PRE_TOT + 255) / 256, 256>>>(cam_code, proj_code,
                                            cam_w0, cam_w1, proj_w0, proj_w1,
                                            CH, Pp, W0c, W1c, W0p, W1p);

    const int TC = S_CAM / 128;   // 1024
    const int TP = S_PROJ / 128;  // 8
    dim3 gmlp(2, TC + TP);        // 2 exact-fit x-tiles of 112

    GArg c0, p0;
    // layer 0, GEMM 0: H = relu(P @ W0^T + b0); cam P gathered from g_camh
    c0 = {nullptr, W0c, nullptr, nullptr, CH, cam_b0, Hc, nullptr,
          S_CAM,  1, 0, 0};
    p0 = {Pp,      W0p, nullptr, nullptr, nullptr, proj_b0, Hp, nullptr,
          S_PROJ, 0, 0, 0};
    tgemm_mlp<3><<<gmlp, 128, MLP_SMEM>>>(c0, p0);        // bias|relu

    // layer 0, GEMM 1: X = P + H @ W1^T + b1  (cam residual staged gather)
    c0 = {Hc, W1c, nullptr, nullptr, CH, cam_b1, X, nullptr,
          S_CAM,  0, 1, 0};
    p0 = {Hp, W1p, Pp,      nullptr, nullptr, proj_b1, Xp, nullptr,
          S_PROJ, 0, 0, 0};
    tgemm_mlp<5><<<gmlp, 128, MLP_SMEM>>>(c0, p0);        // bias|res

    // layer 1, GEMM 0: H = relu(X @ W0^T + b0)
    c0 = {X,  W0c + F2, nullptr, nullptr, nullptr, cam_b0 + FEAT,  Hc, nullptr,
          S_CAM,  0, 0, 0};
    p0 = {Xp, W0p + F2, nullptr, nullptr, nullptr, proj_b0 + FEAT, Hp, nullptr,
          S_PROJ, 0, 0, 0};
    tgemm_mlp<3><<<gmlp, 128, MLP_SMEM>>>(c0, p0);

    // layer 1, GEMM 1: Y = X + H @ W1^T + b1 + P  (+ per-row stats, cam)
    c0 = {Hc, W1c + F2, X,  nullptr, CH, cam_b1 + FEAT,  X,  ST,
          S_CAM,  0, 0, 1};
    p0 = {Hp, W1p + F2, Xp, Pp,      nullptr, proj_b1 + FEAT, Xp, nullptr,
          S_PROJ, 0, 0, 0};
    tgemm_mlp<149><<<gmlp, 128, MLP_SMEM>>>(c0, p0);      // bias|res|res2|stats

    // 3) Proj normalize (cam stats already emitted)
    normalize_proj<<<(S_PROJ + 7) / 8, 256>>>(Xp, Hp, S_PROJ);

    // 4) ZNCC correlation
    dim3 gfin(W_PAT / 128, TC);
    tgemm_fin<<<gfin, 128, FIN_SMEM>>>(X, Hp, ST, out);
}